// round 7
// baseline (speedup 1.0000x reference)
#include <cuda_runtime.h>
#include <cstdint>

#define Bsz 64
#define Ssz 2048
#define Isz 512
#define Hsz 512

// ============================================================
// Phase 1: xW = x @ W + b   (M=131072, K=512, N=512)
// 128x128 block tile, BK=8, 256 threads, 8x8 thread tile,
// packed f32x2 FMA. 2 CTAs/SM hides sync bubbles.
// ============================================================
__global__ __launch_bounds__(256, 2) void sgemm_xw(
    const float* __restrict__ A,
    const float* __restrict__ Wm,
    const float* __restrict__ bias,
    float* __restrict__ C)
{
    constexpr int K = 512, N = 512;
    __shared__ float As[8][128];
    __shared__ float Bs[8][128];

    const int tid  = threadIdx.x;
    const int bm   = blockIdx.y, bn = blockIdx.x;
    const int arow = tid >> 1, acol = (tid & 1) << 2;
    const int brow = tid >> 5, bcol = (tid & 31) << 2;
    const int tx   = tid & 15, ty = tid >> 4;

    const float* Ab = A + (size_t)bm * 128 * K;
    const float* Bb = Wm + bn * 128;

    unsigned long long acc[8][4];
#pragma unroll
    for (int i = 0; i < 8; i++)
#pragma unroll
        for (int j = 0; j < 4; j++) acc[i][j] = 0ull;

    for (int kk = 0; kk < K; kk += 8) {
        float4 av = *(const float4*)(Ab + (size_t)arow * K + kk + acol);
        float4 bv = *(const float4*)(Bb + (size_t)(kk + brow) * N + bcol);
        __syncthreads();
        As[acol + 0][arow] = av.x;
        As[acol + 1][arow] = av.y;
        As[acol + 2][arow] = av.z;
        As[acol + 3][arow] = av.w;
        *(float4*)&Bs[brow][bcol] = bv;
        __syncthreads();
#pragma unroll
        for (int k = 0; k < 8; k++) {
            float4 a0 = *(const float4*)&As[k][ty * 8];
            float4 a1 = *(const float4*)&As[k][ty * 8 + 4];
            ulonglong2 b0 = *(const ulonglong2*)&Bs[k][tx * 8];
            ulonglong2 b1 = *(const ulonglong2*)&Bs[k][tx * 8 + 4];
            float ar[8] = {a0.x, a0.y, a0.z, a0.w, a1.x, a1.y, a1.z, a1.w};
            unsigned long long br[4] = {b0.x, b0.y, b1.x, b1.y};
#pragma unroll
            for (int i = 0; i < 8; i++) {
                unsigned long long ad;
                unsigned int au = __float_as_uint(ar[i]);
                asm("mov.b64 %0, {%1, %1};" : "=l"(ad) : "r"(au));
#pragma unroll
                for (int j = 0; j < 4; j++)
                    asm("fma.rn.f32x2 %0, %1, %2, %0;"
                        : "+l"(acc[i][j]) : "l"(ad), "l"(br[j]));
            }
        }
    }

    const int cb = bn * 128 + tx * 8;
    ulonglong2 bb0 = *(const ulonglong2*)&bias[cb];
    ulonglong2 bb1 = *(const ulonglong2*)&bias[cb + 4];
    unsigned long long bz[4] = {bb0.x, bb0.y, bb1.x, bb1.y};
#pragma unroll
    for (int i = 0; i < 8; i++) {
        size_t row = (size_t)bm * 128 + ty * 8 + i;
        float* Crow = C + row * N + cb;
#pragma unroll
        for (int j = 0; j < 4; j++) {
            unsigned long long v;
            asm("add.rn.f32x2 %0, %1, %2;" : "=l"(v) : "l"(acc[i][j]), "l"(bz[j]));
            *(unsigned long long*)(Crow + 2 * j) = v;
        }
    }
}

// fast tanh: 1 - 2/(exp(2x)+1) via MUFU EX2 + RCP (abs err ~1e-7).
__device__ __forceinline__ float fast_tanh(float x) {
    float e;
    asm("ex2.approx.f32 %0, %1;" : "=f"(e) : "f"(x * 2.8853900817779268f));
    float r;
    asm("rcp.approx.f32 %0, %1;" : "=f"(r) : "f"(e + 1.0f));
    return fmaf(-2.0f, r, 1.0f);
}

__device__ __forceinline__ void mbar_wait(unsigned int addr, unsigned int parity) {
    unsigned int done;
    do {
        asm volatile(
            "{\n\t.reg .pred p;\n\t"
            "mbarrier.try_wait.parity.acquire.cta.shared::cta.b64 p, [%1], %2, 0x989680;\n\t"
            "selp.b32 %0, 1, 0, p;\n\t}"
            : "=r"(done) : "r"(addr), "r"(parity) : "memory");
    } while (!done);
}

// ============================================================
// Phase 2: persistent cluster RNN scan, batch-group pipelined.
// 16 clusters x 8 CTAs, 256 threads/CTA. Cluster owns 4 batches,
// split into 2 groups of 2. Per step:
//   wait(g0) -> FMA(g0) -> epi+send(g0) -> wait(g1) -> FMA(g1)
//   -> epi+send(g1);  g0's exchange flies while g1 computes.
// h layout per group: [buf][kpair][b(2)][kk(2)] so the FMA loop is
// 1 LDS.128 + 2 FFMA2 per k-pair with pre-packed U (no dup movs).
// Exchange: 7 x 512B cp.async.bulk smem->remote smem, complete_tx
// on remote per-group mbarrier (expect 3584 B).
// ============================================================
__global__ void __launch_bounds__(256, 1) __cluster_dims__(8, 1, 1)
rnn_scan(const float* __restrict__ U,      // [512,512] row-major [k][h]
         float* __restrict__ hidden,       // [B,S,H]: in = xW+b, out = h
         float* __restrict__ hlast)        // [B,H]
{
    __shared__ __align__(128) float hbuf[2][2][256][2][2]; // [grp][buf][kp][b][kk]
    __shared__ __align__(16)  float2 red[2][4][64];        // [grp][ks][col]
    __shared__ __align__(16)  unsigned long long mbar[2][2]; // [grp][buf]

    const int tid = threadIdx.x;
    unsigned int rank;
    asm("mov.u32 %0, %%cluster_ctarank;" : "=r"(rank));
    const int cid = blockIdx.x >> 3;
    const int b0  = cid * 4;
    const int ks  = tid >> 6;              // 0..3
    const int c   = tid & 63;
    const int cg  = (int)rank * 64 + c;

    // Pre-pack U k-pairs: Upack[j] = (U[k0][cg], U[k0+1][cg]), k0 = ks*128+2j.
    unsigned long long Upack[64];
#pragma unroll
    for (int j = 0; j < 64; j++) {
        int k0 = ks * 128 + 2 * j;
        unsigned int lo = __float_as_uint(U[(size_t)k0 * Hsz + cg]);
        unsigned int hi = __float_as_uint(U[(size_t)(k0 + 1) * Hsz + cg]);
        asm("mov.b64 %0, {%1, %2};" : "=l"(Upack[j]) : "r"(lo), "r"(hi));
    }

    const unsigned int hb_base =
        (unsigned int)__cvta_generic_to_shared(&hbuf[0][0][0][0][0]);
    const unsigned int mb_base =
        (unsigned int)__cvta_generic_to_shared(&mbar[0][0]);

    // Zero both buffers of both groups; init 4 mbarriers; pre-arm buf-1 pair.
    {
        float* hz = &hbuf[0][0][0][0][0];
        for (int i = tid; i < 2 * 2 * 256 * 4; i += 256) hz[i] = 0.0f;
    }
    if (tid == 0) {
#pragma unroll
        for (int g = 0; g < 2; g++)
#pragma unroll
            for (int b = 0; b < 2; b++)
                asm volatile("mbarrier.init.shared.b64 [%0], %1;"
                             :: "r"(mb_base + g * 16u + b * 8u), "r"(1u)
                             : "memory");
        asm volatile("mbarrier.arrive.expect_tx.shared.b64 _, [%0], %1;"
                     :: "r"(mb_base + 8u), "r"(3584u) : "memory");
        asm volatile("mbarrier.arrive.expect_tx.shared.b64 _, [%0], %1;"
                     :: "r"(mb_base + 24u), "r"(3584u) : "memory");
    }
    __syncthreads();
    asm volatile("barrier.cluster.arrive.aligned;" ::: "memory");
    asm volatile("barrier.cluster.wait.aligned;" ::: "memory");

    // Epilogue thread state (tid < 128): one (col, batch) value per group.
    const int ecol = tid & 63;
    const int eb   = (tid >> 6) & 1;
    const int egc  = (int)rank * 64 + ecol;
    size_t ga0 = 0, ga1 = 0;
    if (tid < 128) {
        ga0 = ((size_t)(b0 + eb) * Ssz) * Hsz + egc;      // group 0 batch
        ga1 = ga0 + 2 * (size_t)Ssz * Hsz;                // group 1 batch
    }
    unsigned int php[2] = {0u, 0u};

    for (int t = 0; t < Ssz; t++) {
        const int q = t & 1;
        const unsigned int mb0q = mb_base + (unsigned int)q * 8u;
        const unsigned int mb1q = mb_base + 16u + (unsigned int)q * 8u;

        // xw prefetch for both groups (independent of waits).
        float xw0 = 0.f, xw1 = 0.f;
        if (tid < 128) {
            xw0 = __ldg(hidden + ga0);
            xw1 = __ldg(hidden + ga1);
        }
        const unsigned int pq = php[q];

        // ================= group 0 =================
        if (t > 0) mbar_wait(mb0q, pq);
        if (tid == 0)
            asm volatile("mbarrier.arrive.expect_tx.shared.b64 _, [%0], %1;"
                         :: "r"(mb0q), "r"(3584u) : "memory");
        {
            const ulonglong2* hk =
                (const ulonglong2*)&hbuf[0][q][ks * 64][0][0];
            unsigned long long a0a = 0ull, a0b = 0ull, a1a = 0ull, a1b = 0ull;
#pragma unroll
            for (int j = 0; j < 64; j += 2) {
                ulonglong2 e0 = hk[j];
                ulonglong2 e1 = hk[j + 1];
                asm("fma.rn.f32x2 %0, %1, %2, %0;" : "+l"(a0a) : "l"(Upack[j]),     "l"(e0.x));
                asm("fma.rn.f32x2 %0, %1, %2, %0;" : "+l"(a1a) : "l"(Upack[j]),     "l"(e0.y));
                asm("fma.rn.f32x2 %0, %1, %2, %0;" : "+l"(a0b) : "l"(Upack[j + 1]), "l"(e1.x));
                asm("fma.rn.f32x2 %0, %1, %2, %0;" : "+l"(a1b) : "l"(Upack[j + 1]), "l"(e1.y));
            }
            unsigned long long s0, s1;
            asm("add.rn.f32x2 %0, %1, %2;" : "=l"(s0) : "l"(a0a), "l"(a0b));
            asm("add.rn.f32x2 %0, %1, %2;" : "=l"(s1) : "l"(a1a), "l"(a1b));
            unsigned int l, h;
            float r0, r1;
            asm("mov.b64 {%0, %1}, %2;" : "=r"(l), "=r"(h) : "l"(s0));
            r0 = __uint_as_float(l) + __uint_as_float(h);
            asm("mov.b64 {%0, %1}, %2;" : "=r"(l), "=r"(h) : "l"(s1));
            r1 = __uint_as_float(l) + __uint_as_float(h);
            red[0][ks][c] = make_float2(r0, r1);
        }
        __syncthreads();

        if (tid < 128) {
            float2 p0 = red[0][0][ecol], p1 = red[0][1][ecol];
            float2 p2 = red[0][2][ecol], p3 = red[0][3][ecol];
            float s = eb ? ((p0.y + p1.y) + (p2.y + p3.y))
                         : ((p0.x + p1.x) + (p2.x + p3.x));
            float v = fast_tanh(xw0 + s);
            hbuf[0][q ^ 1][egc >> 1][eb][egc & 1] = v;
            hidden[ga0] = v;
            if (t == Ssz - 1)
                hlast[(size_t)(b0 + eb) * Hsz + egc] = v;
            else
                ga0 += Hsz;
            asm volatile("bar.sync 1, 128;" ::: "memory");
        }
        if (tid < 7) {
            asm volatile("fence.proxy.async.shared::cta;" ::: "memory");
            const unsigned int src =
                hb_base + (unsigned int)(q ^ 1) * 4096u + rank * 512u;
            const unsigned int pr = (rank + 1u + (unsigned int)tid) & 7u;
            unsigned int dst, rmb;
            asm("mapa.shared::cluster.u32 %0, %1, %2;"
                : "=r"(dst) : "r"(src), "r"(pr));
            asm("mapa.shared::cluster.u32 %0, %1, %2;"
                : "=r"(rmb) : "r"(mb_base + (unsigned int)(q ^ 1) * 8u), "r"(pr));
            asm volatile(
                "cp.async.bulk.shared::cluster.shared::cta.mbarrier::complete_tx::bytes "
                "[%0], [%1], %2, [%3];"
                :: "r"(dst), "r"(src), "r"(512u), "r"(rmb) : "memory");
        }

        // ================= group 1 =================
        if (t > 0) { mbar_wait(mb1q, pq); php[q] = pq ^ 1u; }
        if (tid == 0)
            asm volatile("mbarrier.arrive.expect_tx.shared.b64 _, [%0], %1;"
                         :: "r"(mb1q), "r"(3584u) : "memory");
        {
            const ulonglong2* hk =
                (const ulonglong2*)&hbuf[1][q][ks * 64][0][0];
            unsigned long long a0a = 0ull, a0b = 0ull, a1a = 0ull, a1b = 0ull;
#pragma unroll
            for (int j = 0; j < 64; j += 2) {
                ulonglong2 e0 = hk[j];
                ulonglong2 e1 = hk[j + 1];
                asm("fma.rn.f32x2 %0, %1, %2, %0;" : "+l"(a0a) : "l"(Upack[j]),     "l"(e0.x));
                asm("fma.rn.f32x2 %0, %1, %2, %0;" : "+l"(a1a) : "l"(Upack[j]),     "l"(e0.y));
                asm("fma.rn.f32x2 %0, %1, %2, %0;" : "+l"(a0b) : "l"(Upack[j + 1]), "l"(e1.x));
                asm("fma.rn.f32x2 %0, %1, %2, %0;" : "+l"(a1b) : "l"(Upack[j + 1]), "l"(e1.y));
            }
            unsigned long long s0, s1;
            asm("add.rn.f32x2 %0, %1, %2;" : "=l"(s0) : "l"(a0a), "l"(a0b));
            asm("add.rn.f32x2 %0, %1, %2;" : "=l"(s1) : "l"(a1a), "l"(a1b));
            unsigned int l, h;
            float r0, r1;
            asm("mov.b64 {%0, %1}, %2;" : "=r"(l), "=r"(h) : "l"(s0));
            r0 = __uint_as_float(l) + __uint_as_float(h);
            asm("mov.b64 {%0, %1}, %2;" : "=r"(l), "=r"(h) : "l"(s1));
            r1 = __uint_as_float(l) + __uint_as_float(h);
            red[1][ks][c] = make_float2(r0, r1);
        }
        __syncthreads();

        if (tid < 128) {
            float2 p0 = red[1][0][ecol], p1 = red[1][1][ecol];
            float2 p2 = red[1][2][ecol], p3 = red[1][3][ecol];
            float s = eb ? ((p0.y + p1.y) + (p2.y + p3.y))
                         : ((p0.x + p1.x) + (p2.x + p3.x));
            float v = fast_tanh(xw1 + s);
            hbuf[1][q ^ 1][egc >> 1][eb][egc & 1] = v;
            hidden[ga1] = v;
            if (t == Ssz - 1)
                hlast[(size_t)(b0 + 2 + eb) * Hsz + egc] = v;
            else
                ga1 += Hsz;
            asm volatile("bar.sync 1, 128;" ::: "memory");
        }
        if (tid < 7) {
            asm volatile("fence.proxy.async.shared::cta;" ::: "memory");
            const unsigned int src =
                hb_base + 8192u + (unsigned int)(q ^ 1) * 4096u + rank * 512u;
            const unsigned int pr = (rank + 1u + (unsigned int)tid) & 7u;
            unsigned int dst, rmb;
            asm("mapa.shared::cluster.u32 %0, %1, %2;"
                : "=r"(dst) : "r"(src), "r"(pr));
            asm("mapa.shared::cluster.u32 %0, %1, %2;"
                : "=r"(rmb) : "r"(mb_base + 16u + (unsigned int)(q ^ 1) * 8u), "r"(pr));
            asm volatile(
                "cp.async.bulk.shared::cluster.shared::cta.mbarrier::complete_tx::bytes "
                "[%0], [%1], %2, [%3];"
                :: "r"(dst), "r"(src), "r"(512u), "r"(rmb) : "memory");
        }
    }

    // Drain the final inbound phase (t=2047 sends target buffer 0 barriers),
    // then cluster-sync before exit.
    mbar_wait(mb_base, php[0]);
    mbar_wait(mb_base + 16u, php[0]);
    asm volatile("barrier.cluster.arrive.aligned;" ::: "memory");
    asm volatile("barrier.cluster.wait.aligned;" ::: "memory");
}

extern "C" void kernel_launch(void* const* d_in, const int* in_sizes, int n_in,
                              void* d_out, int out_size) {
    const float* x  = (const float*)d_in[0];   // [64,2048,512]
    const float* Wi = (const float*)d_in[1];   // [512,512]
    const float* Ui = (const float*)d_in[2];   // [512,512]
    const float* bi = (const float*)d_in[3];   // [512]

    float* hidden = (float*)d_out;                        // [B,S,H]
    float* hlast  = hidden + (size_t)Bsz * Ssz * Hsz;     // [B,H]

    dim3 g1(Hsz / 128, (Bsz * Ssz) / 128);   // (4, 1024)
    sgemm_xw<<<g1, 256>>>(x, Wi, bi, hidden);

    rnn_scan<<<128, 256>>>(Ui, hidden, hlast);
}